// round 1
// baseline (speedup 1.0000x reference)
#include <cuda_runtime.h>

// ---------------------------------------------------------------------------
// MOE_DISTRIBUTE_CASCADE_GRAPH: stable counting-sort rank + gather-reduce.
//
// inv[i] = base[e_i] + #{j < i : e_j == e_i}        (i in [0, N), N = B*K)
// out[b,h] = sum_k scales[b,k] * G[inv[b*K+k], h]
// output = (out, out) concatenated  (2*B*H floats)
// ---------------------------------------------------------------------------

#define MAXE      256      // max experts supported (dataset uses 64)
#define CHUNK     256      // elements per rank chunk
#define MAXN      65536    // max B*K supported (dataset uses 32768)
#define MAXCHUNKS (MAXN / CHUNK)

__device__ int g_chunk_hist[MAXCHUNKS][MAXE];
__device__ int g_chunk_base[MAXCHUNKS][MAXE];
__device__ int g_inv[MAXN];

// --- Kernel 1: per-chunk expert histogram -----------------------------------
__global__ void hist_kernel(const int* __restrict__ ids, int n) {
    __shared__ int sh[MAXE];
    const int c = blockIdx.x;
    for (int e = threadIdx.x; e < MAXE; e += blockDim.x) sh[e] = 0;
    __syncthreads();
    const int i = c * CHUNK + threadIdx.x;
    if (i < n) atomicAdd(&sh[ids[i]], 1);
    __syncthreads();
    for (int e = threadIdx.x; e < MAXE; e += blockDim.x)
        g_chunk_hist[c][e] = sh[e];
}

// --- Kernel 2: per-expert exclusive scan over chunks + expert base prefix ---
// One block of MAXE threads; thread e owns expert e.
__global__ void scan_kernel(int nchunks) {
    __shared__ int totals[MAXE];
    const int e = threadIdx.x;
    int run = 0;
    for (int c = 0; c < nchunks; c++) {
        g_chunk_base[c][e] = run;
        run += g_chunk_hist[c][e];
    }
    totals[e] = run;
    __syncthreads();
    if (e == 0) {
        int acc = 0;
        for (int x = 0; x < MAXE; x++) { int t = totals[x]; totals[x] = acc; acc += t; }
    }
    __syncthreads();
    const int base = totals[e];
    for (int c = 0; c < nchunks; c++) g_chunk_base[c][e] += base;
}

// --- Kernel 3: stable in-chunk rank assignment -------------------------------
__global__ void rank_kernel(const int* __restrict__ ids, int n) {
    __shared__ int cnt[MAXE];
    __shared__ int lid[CHUNK];
    const int c = blockIdx.x;
    for (int e = threadIdx.x; e < MAXE; e += blockDim.x)
        cnt[e] = g_chunk_base[c][e];
    const int i = c * CHUNK + threadIdx.x;
    if (threadIdx.x < CHUNK && i < n) lid[threadIdx.x] = ids[i];
    __syncthreads();
    if (threadIdx.x == 0) {
        const int lim = min(CHUNK, n - c * CHUNK);
        #pragma unroll 4
        for (int p = 0; p < lim; p++) {
            const int e = lid[p];
            const int r = cnt[e];
            cnt[e] = r + 1;
            g_inv[c * CHUNK + p] = r;
        }
    }
}

// --- Kernel 4: gather-reduce combine (HBM-bound; the roofline kernel) -------
// One block per token b. Each thread owns float4 column groups; 8 independent
// gathers per group keep MLP high so DRAM latency is fully overlapped.
__global__ void __launch_bounds__(1024, 1)
combine_kernel(const float* __restrict__ G,
               const float* __restrict__ scales,
               float* __restrict__ out,
               int B, int K, int H4, int dup) {
    const int b = blockIdx.x;
    __shared__ int   rows[16];
    __shared__ float sc[16];
    if (threadIdx.x < (unsigned)K) {
        rows[threadIdx.x] = g_inv[b * K + threadIdx.x];
        sc[threadIdx.x]   = scales[b * K + threadIdx.x];
    }
    __syncthreads();

    const float4* __restrict__ Gv = reinterpret_cast<const float4*>(G);
    float4* __restrict__ ov = reinterpret_cast<float4*>(out);

    for (int h = threadIdx.x; h < H4; h += blockDim.x) {
        float4 acc = make_float4(0.f, 0.f, 0.f, 0.f);
        #pragma unroll 8
        for (int k = 0; k < K; k++) {
            const float  s = sc[k];
            const float4 v = __ldg(&Gv[(size_t)rows[k] * H4 + h]);
            acc.x = fmaf(s, v.x, acc.x);
            acc.y = fmaf(s, v.y, acc.y);
            acc.z = fmaf(s, v.z, acc.z);
            acc.w = fmaf(s, v.w, acc.w);
        }
        const size_t o = (size_t)b * H4 + h;
        ov[o] = acc;
        if (dup) ov[(size_t)B * H4 + o] = acc;
    }
}

// ---------------------------------------------------------------------------
extern "C" void kernel_launch(void* const* d_in, const int* in_sizes, int n_in,
                              void* d_out, int out_size) {
    // metadata order: x[B,H] f32, expert_ids[B,K] i32, expert_scales[B,K] f32,
    //                 golden_expand_x[B*K,H] f32, moe_expert_num i32
    const int*   ids    = (const int*)  d_in[1];
    const float* scales = (const float*)d_in[2];
    const float* G      = (const float*)d_in[3];
    float*       out    = (float*)d_out;

    const int N  = in_sizes[1];                     // B*K = 32768
    const long long GH = (long long)in_sizes[3];    // N*H
    const int H  = (int)(GH / N);                   // 4096
    const int B  = in_sizes[0] / H;                 // 4096
    const int K  = N / B;                           // 8
    const int H4 = H >> 2;
    const int nchunks = (N + CHUNK - 1) / CHUNK;    // 128
    const int dup = (out_size >= 2 * B * H) ? 1 : 0;

    hist_kernel<<<nchunks, CHUNK>>>(ids, N);
    scan_kernel<<<1, MAXE>>>(nchunks);
    rank_kernel<<<nchunks, CHUNK>>>(ids, N);

    const int threads = (H4 >= 1024) ? 1024 : ((H4 + 31) / 32) * 32;
    combine_kernel<<<B, threads>>>(G, scales, out, B, K, H4, dup);
}

// round 2
// speedup vs baseline: 1.1072x; 1.1072x over previous
#include <cuda_runtime.h>

// ---------------------------------------------------------------------------
// MOE_DISTRIBUTE_CASCADE_GRAPH
//   inv[i]   = stable counting-sort rank of expert_ids.flat[i]   (N = B*K)
//   out[b,h] = sum_k scales[b,k] * G[inv[b*K+k], h]
//   output   = (out, out) concatenated (2*B*H floats)
// ---------------------------------------------------------------------------

#define NBINS   256        // max experts supported (dataset uses 64)
#define RWARPS  32         // warps in the rank block
#define RTHREADS (RWARPS * 32)
#define MAXN    65536      // max B*K supported (dataset uses 32768)

__device__ int g_inv[MAXN];

// --- Kernel 1: fused stable counting-sort rank (single block, all in SMEM) --
// Warp w owns the contiguous chunk [w*cpw, (w+1)*cpw). Phases:
//   A) per-warp histogram into smem
//   B) per-expert exclusive scan across warp-chunks (in place) + expert-base
//      exclusive scan (block-wide Hillis-Steele over NBINS totals)
//   C) stable rank assignment via __match_any_sync (index order preserved:
//      warps own ascending chunks, rounds ascend, lower lanes are earlier)
__global__ void __launch_bounds__(RTHREADS, 1)
rank_fused_kernel(const int* __restrict__ ids, int n) {
    __shared__ int cnt[RWARPS * NBINS];   // hist -> base -> running counters
    __shared__ int totals[NBINS];
    __shared__ int totals2[NBINS];

    const int tid  = threadIdx.x;
    const int w    = tid >> 5;
    const int lane = tid & 31;
    const int cpw  = (n + RWARPS - 1) / RWARPS;   // elems per warp chunk

    // zero histograms
    for (int i = tid; i < RWARPS * NBINS; i += RTHREADS) cnt[i] = 0;
    __syncthreads();

    // A) per-warp histogram (atomics confined to this warp's 256-bin row)
    const int beg = w * cpw;
    const int end = min(beg + cpw, n);
    for (int i = beg + lane; i < end; i += 32)
        atomicAdd(&cnt[w * NBINS + ids[i]], 1);
    __syncthreads();

    // B1) per-expert exclusive scan over the 32 warp rows, in place.
    //     thread e (< NBINS) owns expert e; chain is SMEM-latency only.
    if (tid < NBINS) {
        int run = 0;
        #pragma unroll
        for (int ww = 0; ww < RWARPS; ww++) {
            const int h = cnt[ww * NBINS + tid];
            cnt[ww * NBINS + tid] = run;
            run += h;
        }
        totals[tid] = run;
    }
    __syncthreads();

    // B2) exclusive scan of expert totals (Hillis-Steele, NBINS threads)
    #pragma unroll
    for (int d = 1; d < NBINS; d <<= 1) {
        int v = 0;
        if (tid < NBINS) v = (tid >= d) ? totals[tid - d] : 0;
        __syncthreads();
        if (tid < NBINS) totals2[tid] = totals[tid] + v;
        __syncthreads();
        // ping-pong back
        if (tid < NBINS) totals[tid] = totals2[tid];
        __syncthreads();
    }
    // totals[] now holds INCLUSIVE scan; exclusive base = totals[e] - count[e]
    // easier: base[e] = (e == 0) ? 0 : totals[e-1]
    if (tid < NBINS) {
        const int base = (tid == 0) ? 0 : totals[tid - 1];
        #pragma unroll
        for (int ww = 0; ww < RWARPS; ww++)
            cnt[ww * NBINS + tid] += base;
    }
    __syncthreads();

    // C) stable rank assignment
    int* mycnt = &cnt[w * NBINS];
    for (int i = beg + lane; ; i += 32) {
        const bool valid = (i < end);
        // give invalid lanes unique keys so they form singleton groups
        const int key = valid ? ids[i] : (NBINS + 32 + lane);
        const unsigned mask = __match_any_sync(0xffffffffu, key);
        const int lower  = __popc(mask & ((1u << lane) - 1u));
        const int leader = __ffs(mask) - 1;
        int r0 = 0;
        if (valid && lane == leader) {
            r0 = mycnt[key];
            mycnt[key] = r0 + __popc(mask);
        }
        r0 = __shfl_sync(0xffffffffu, r0, leader);
        if (valid) g_inv[i] = r0 + lower;
        // uniform exit: all lanes agree once the whole warp is out of range
        if (__all_sync(0xffffffffu, i + 32 >= end)) {
            if (i + 32 < end) {} // unreachable; keeps structure simple
            break;
        }
    }
}

// --- Kernel 2: gather-reduce combine (HBM streaming roofline kernel) --------
// One block per token b; thread t owns float4 column t. 8 independent
// streaming gathers (read-once -> __ldcs), write-once outputs -> __stcs.
__global__ void __launch_bounds__(1024, 1)
combine_kernel(const float* __restrict__ G,
               const float* __restrict__ scales,
               float* __restrict__ out,
               int B, int K, int H4, int dup) {
    const int b = blockIdx.x;
    __shared__ int   rows[16];
    __shared__ float sc[16];
    if (threadIdx.x < (unsigned)K) {
        rows[threadIdx.x] = g_inv[b * K + threadIdx.x];
        sc[threadIdx.x]   = scales[b * K + threadIdx.x];
    }
    __syncthreads();

    const float4* __restrict__ Gv = reinterpret_cast<const float4*>(G);
    float4* __restrict__ ov = reinterpret_cast<float4*>(out);

    for (int h = threadIdx.x; h < H4; h += blockDim.x) {
        float4 acc = make_float4(0.f, 0.f, 0.f, 0.f);
        #pragma unroll 8
        for (int k = 0; k < K; k++) {
            const float  s = sc[k];
            const float4 v = __ldcs(&Gv[(size_t)rows[k] * H4 + h]);
            acc.x = fmaf(s, v.x, acc.x);
            acc.y = fmaf(s, v.y, acc.y);
            acc.z = fmaf(s, v.z, acc.z);
            acc.w = fmaf(s, v.w, acc.w);
        }
        const size_t o = (size_t)b * H4 + h;
        __stcs(&ov[o], acc);
        if (dup) __stcs(&ov[(size_t)B * H4 + o], acc);
    }
}

// ---------------------------------------------------------------------------
extern "C" void kernel_launch(void* const* d_in, const int* in_sizes, int n_in,
                              void* d_out, int out_size) {
    // metadata order: x[B,H] f32, expert_ids[B,K] i32, expert_scales[B,K] f32,
    //                 golden_expand_x[B*K,H] f32, moe_expert_num i32
    const int*   ids    = (const int*)  d_in[1];
    const float* scales = (const float*)d_in[2];
    const float* G      = (const float*)d_in[3];
    float*       out    = (float*)d_out;

    const int N  = in_sizes[1];                     // B*K = 32768
    const long long GH = (long long)in_sizes[3];    // N*H
    const int H  = (int)(GH / N);                   // 4096
    const int B  = in_sizes[0] / H;                 // 4096
    const int K  = N / B;                           // 8
    const int H4 = H >> 2;
    const int dup = (out_size >= 2 * B * H) ? 1 : 0;

    rank_fused_kernel<<<1, RTHREADS>>>(ids, N);

    const int threads = (H4 >= 1024) ? 1024 : ((H4 + 31) / 32) * 32;
    combine_kernel<<<B, threads>>>(G, scales, out, B, K, H4, dup);
}